// round 7
// baseline (speedup 1.0000x reference)
#include <cuda_runtime.h>
#include <cstdint>

#define MAXN 100000
#define MAXE 1600000
#define D    128
#define G    64
#define REP  32
#define SCB  1024
#define TM   64      // nodes per fused-kernel block

// ---------------- device scratch ----------------
__device__ float g_h1[MAXN * D];        // layer-1 GEMM output
__device__ float g_h2[MAXN * D];        // pre-scaled layer-1 activation: dis_i * leaky(conv1_i)
__device__ int   g_deg[MAXN];
__device__ float g_dis[MAXN];
__device__ int   g_off[MAXN + 1];
__device__ int   g_cursor[MAXN];
__device__ int   g_adj[MAXE];           // src index only (weightless CSR)
__device__ float g_gsum[G * REP];
__device__ int   g_bsum[128];
__device__ int   g_bbase[128];
__device__ int   g_is64;

// ---------------- dtype-agnostic index read ----------------
__device__ __forceinline__ int idx_at(const void* p, size_t i) {
    if (g_is64) return (int)((const long long*)p)[i];
    return ((const int*)p)[i];
}

// ---------------- init (+dtype detect) ----------------
__global__ void k_init(const int* __restrict__ ei32, int n) {
    int i = blockIdx.x * blockDim.x + threadIdx.x;
    if (i == 0) {
        int allz = 1;
        for (int j = 1; j < 32; j += 2)
            if (ei32[j] != 0) allz = 0;
        g_is64 = allz;
    }
    if (i < n) g_deg[i] = 1;
    if (i < G * REP) g_gsum[i] = 0.f;
}

// ---------------- in-degree count ----------------
__global__ void k_deg(const void* __restrict__ ei, int e) {
    int i = blockIdx.x * blockDim.x + threadIdx.x;
    if (i < e) atomicAdd(&g_deg[idx_at(ei, (size_t)e + i)], 1);
}

// ---------------- scan phase 1: block sums of (deg-1); also dis=rsqrt(deg) ----------------
__global__ void k_scan1(int n) {
    int i = blockIdx.x * SCB + threadIdx.x;
    int v = 0;
    if (i < n) {
        int d = g_deg[i];
        g_dis[i] = rsqrtf((float)d);
        v = d - 1;
    }
    int s = v;
#pragma unroll
    for (int o = 16; o; o >>= 1) s += __shfl_down_sync(0xffffffffu, s, o);
    __shared__ int ws[SCB / 32];
    int w = threadIdx.x >> 5, l = threadIdx.x & 31;
    if (l == 0) ws[w] = s;
    __syncthreads();
    if (w == 0) {
        int t = (l < SCB / 32) ? ws[l] : 0;
#pragma unroll
        for (int o = 16; o; o >>= 1) t += __shfl_down_sync(0xffffffffu, t, o);
        if (l == 0) g_bsum[blockIdx.x] = t;
    }
}

// ---------------- scan phase 2 ----------------
__global__ void k_scan2(int nb, int n) {
    __shared__ int sm[128];
    int t = threadIdx.x;
    int v = (t < nb) ? g_bsum[t] : 0;
    sm[t] = v;
    __syncthreads();
    for (int o = 1; o < 128; o <<= 1) {
        int u = (t >= o) ? sm[t - o] : 0;
        __syncthreads();
        if (t >= o) sm[t] += u;
        __syncthreads();
    }
    g_bbase[t] = sm[t] - v;
    if (t == 127) g_off[n] = sm[127];
}

// ---------------- scan phase 3 (also seeds cursor = off) ----------------
__global__ void k_scan3(int n) {
    int i = blockIdx.x * SCB + threadIdx.x;
    int v = (i < n) ? (g_deg[i] - 1) : 0;
    int incl = v;
#pragma unroll
    for (int o = 1; o < 32; o <<= 1) {
        int u = __shfl_up_sync(0xffffffffu, incl, o);
        if ((threadIdx.x & 31) >= o) incl += u;
    }
    __shared__ int ws[SCB / 32];
    int w = threadIdx.x >> 5, l = threadIdx.x & 31;
    if (l == 31) ws[w] = incl;
    __syncthreads();
    if (w == 0) {
        int s = (l < SCB / 32) ? ws[l] : 0;
        int si = s;
#pragma unroll
        for (int o = 1; o < 32; o <<= 1) {
            int u = __shfl_up_sync(0xffffffffu, si, o);
            if (l >= o) si += u;
        }
        ws[l] = si - s;
    }
    __syncthreads();
    if (i < n) {
        int off = g_bbase[blockIdx.x] + ws[w] + (incl - v);
        g_off[i] = off;
        g_cursor[i] = off;      // absolute write cursor
    }
}

// ---------------- fill CSR (src only) ----------------
__global__ void k_fill(const void* __restrict__ ei, int e) {
    int i = blockIdx.x * blockDim.x + threadIdx.x;
    if (i < e) {
        int r = idx_at(ei, i);
        int c = idx_at(ei, (size_t)e + i);
        int pos = atomicAdd(&g_cursor[c], 1);
        g_adj[pos] = r;
    }
}

// ---------------- GEMM: h1[n x 128] = x[n x 128] @ W1 (no bias) ----------------
#define BM 128
#define BK 16
__global__ __launch_bounds__(256, 2) void k_gemm(const float* __restrict__ A,
                                                 const float* __restrict__ W,
                                                 float* __restrict__ Cout, int n) {
    __shared__ float As[BM][BK + 1];
    __shared__ float Ws[BK][D];
    int tid = threadIdx.x;
    int tx = tid & 15;
    int ty = tid >> 4;
    int row0 = blockIdx.x * BM;
    float acc[8][8];
#pragma unroll
    for (int r = 0; r < 8; r++)
#pragma unroll
        for (int j = 0; j < 8; j++) acc[r][j] = 0.f;

    for (int kb = 0; kb < D; kb += BK) {
#pragma unroll
        for (int l = 0; l < 2; l++) {
            int idx4 = tid + l * 256;
            int m = idx4 >> 2, c4 = idx4 & 3;
            float4 v = make_float4(0.f, 0.f, 0.f, 0.f);
            int gr = row0 + m;
            if (gr < n) v = *(const float4*)&A[(size_t)gr * D + kb + c4 * 4];
            As[m][c4 * 4 + 0] = v.x; As[m][c4 * 4 + 1] = v.y;
            As[m][c4 * 4 + 2] = v.z; As[m][c4 * 4 + 3] = v.w;
        }
#pragma unroll
        for (int l = 0; l < 2; l++) {
            int idx4 = tid + l * 256;
            int k = idx4 >> 5, n4 = idx4 & 31;
            *(float4*)&Ws[k][n4 * 4] = *(const float4*)&W[(size_t)(kb + k) * D + n4 * 4];
        }
        __syncthreads();
#pragma unroll
        for (int k = 0; k < BK; k++) {
            float a[8], b[8];
#pragma unroll
            for (int r = 0; r < 8; r++) a[r] = As[ty * 8 + r][k];
            *(float4*)&b[0] = *(float4*)&Ws[k][tx * 8];
            *(float4*)&b[4] = *(float4*)&Ws[k][tx * 8 + 4];
#pragma unroll
            for (int r = 0; r < 8; r++)
#pragma unroll
                for (int j = 0; j < 8; j++) acc[r][j] += a[r] * b[j];
        }
        __syncthreads();
    }
#pragma unroll
    for (int r = 0; r < 8; r++) {
        int row = row0 + ty * 8 + r;
        if (row < n) {
            *(float4*)&Cout[(size_t)row * D + tx * 8] =
                make_float4(acc[r][0], acc[r][1], acc[r][2], acc[r][3]);
            *(float4*)&Cout[(size_t)row * D + tx * 8 + 4] =
                make_float4(acc[r][4], acc[r][5], acc[r][6], acc[r][7]);
        }
    }
}

__device__ __forceinline__ float leaky(float x) { return x >= 0.f ? x : 0.01f * x; }

// ---------------- gather1: h2 = dis .* leaky(dis.*(Σ dis_j h1_j + dis_i h1_i) + b1) ----------------
__global__ __launch_bounds__(256) void k_gather1(const float4* __restrict__ h1,
                                                 const float* __restrict__ b1,
                                                 float4* __restrict__ h2, int n) {
    int node = blockIdx.x * 8 + (threadIdx.x >> 5);
    if (node >= n) return;
    int lane = threadIdx.x & 31;

    float di = g_dis[node];
    float4 v = h1[(size_t)node * 32 + lane];
    float4 acc;
    acc.x = v.x * di; acc.y = v.y * di; acc.z = v.z * di; acc.w = v.w * di;

    int s = g_off[node], e = g_off[node + 1];
    int j = s;
    for (; j + 4 <= e; j += 4) {
        int s0 = g_adj[j], s1 = g_adj[j + 1], s2 = g_adj[j + 2], s3 = g_adj[j + 3];
        float d0 = g_dis[s0], d1 = g_dis[s1], d2 = g_dis[s2], d3 = g_dis[s3];
        float4 v0 = h1[(size_t)s0 * 32 + lane];
        float4 v1 = h1[(size_t)s1 * 32 + lane];
        float4 v2 = h1[(size_t)s2 * 32 + lane];
        float4 v3 = h1[(size_t)s3 * 32 + lane];
        acc.x += v0.x * d0 + v1.x * d1 + v2.x * d2 + v3.x * d3;
        acc.y += v0.y * d0 + v1.y * d1 + v2.y * d2 + v3.y * d3;
        acc.z += v0.z * d0 + v1.z * d1 + v2.z * d2 + v3.z * d3;
        acc.w += v0.w * d0 + v1.w * d1 + v2.w * d2 + v3.w * d3;
    }
    for (; j < e; j++) {
        int s0 = g_adj[j];
        float d0 = g_dis[s0];
        float4 v0 = h1[(size_t)s0 * 32 + lane];
        acc.x += v0.x * d0; acc.y += v0.y * d0;
        acc.z += v0.z * d0; acc.w += v0.w * d0;
    }
    float4 bb = ((const float4*)b1)[lane];
    float4 o;
    o.x = di * leaky(di * acc.x + bb.x);
    o.y = di * leaky(di * acc.y + bb.y);
    o.z = di * leaky(di * acc.z + bb.z);
    o.w = di * leaky(di * acc.w + bb.w);
    h2[(size_t)node * 32 + lane] = o;
}

// ---------------- fused layer 2: plain-sum gather -> smem -> FFMA GEMM -> pool ----------------
__global__ __launch_bounds__(256, 2) void k_fused2(
    const float4* __restrict__ in, const float* __restrict__ W,
    const float* __restrict__ bias, const float* __restrict__ fcW,
    const void* __restrict__ batch, int n)
{
    __shared__ float At[D][66];     // feature-major agg tile
    __shared__ float Ws[16][D];
    __shared__ float rowsum[TM];

    int tid = threadIdx.x;
    int warp = tid >> 5, lane = tid & 31;
    int row0 = blockIdx.x * TM;

    // gather: agg_i = dis_i * (h2s_i + Σ_j h2s_j)  (h2s pre-scaled, no per-edge weight)
    for (int nd = warp; nd < TM; nd += 8) {
        int node = row0 + nd;
        float4 acc = make_float4(0.f, 0.f, 0.f, 0.f);
        if (node < n) {
            float di = g_dis[node];
            acc = in[(size_t)node * 32 + lane];
            int s = g_off[node], e = g_off[node + 1];
            int j = s;
            for (; j + 4 <= e; j += 4) {
                int s0 = g_adj[j], s1 = g_adj[j + 1], s2 = g_adj[j + 2], s3 = g_adj[j + 3];
                float4 v0 = in[(size_t)s0 * 32 + lane];
                float4 v1 = in[(size_t)s1 * 32 + lane];
                float4 v2 = in[(size_t)s2 * 32 + lane];
                float4 v3 = in[(size_t)s3 * 32 + lane];
                acc.x += v0.x + v1.x + v2.x + v3.x;
                acc.y += v0.y + v1.y + v2.y + v3.y;
                acc.z += v0.z + v1.z + v2.z + v3.z;
                acc.w += v0.w + v1.w + v2.w + v3.w;
            }
            for (; j < e; j++) {
                int s0 = g_adj[j];
                float4 v0 = in[(size_t)s0 * 32 + lane];
                acc.x += v0.x; acc.y += v0.y; acc.z += v0.z; acc.w += v0.w;
            }
            acc.x *= di; acc.y *= di; acc.z *= di; acc.w *= di;
        }
        int c = lane * 4;
        At[c + 0][nd] = acc.x;
        At[c + 1][nd] = acc.y;
        At[c + 2][nd] = acc.z;
        At[c + 3][nd] = acc.w;
    }
    if (tid < TM) rowsum[tid] = 0.f;

    // GEMM C[64x128] = At^T @ W2
    int tx = tid & 15;
    int ty = tid >> 4;
    float acc[4][8];
#pragma unroll
    for (int r = 0; r < 4; r++)
#pragma unroll
        for (int j = 0; j < 8; j++) acc[r][j] = 0.f;

    for (int kb = 0; kb < D; kb += 16) {
#pragma unroll
        for (int l = 0; l < 2; l++) {
            int idx4 = tid + l * 256;
            int k = idx4 >> 5, c4 = idx4 & 31;
            *(float4*)&Ws[k][c4 * 4] = *(const float4*)&W[(size_t)(kb + k) * D + c4 * 4];
        }
        __syncthreads();
#pragma unroll
        for (int k = 0; k < 16; k++) {
            float a[4], b[8];
#pragma unroll
            for (int r = 0; r < 4; r++) a[r] = At[kb + k][tx * 4 + r];
            *(float4*)&b[0] = *(float4*)&Ws[k][ty * 8];
            *(float4*)&b[4] = *(float4*)&Ws[k][ty * 8 + 4];
#pragma unroll
            for (int r = 0; r < 4; r++)
#pragma unroll
                for (int j = 0; j < 8; j++) acc[r][j] += a[r] * b[j];
        }
        __syncthreads();
    }

    // pool epilogue: rowsum = leaky(C + b2) . fcW  -> per-graph accumulators
    float fj[8], bj[8];
#pragma unroll
    for (int j = 0; j < 8; j++) { fj[j] = fcW[ty * 8 + j]; bj[j] = bias[ty * 8 + j]; }
#pragma unroll
    for (int r = 0; r < 4; r++) {
        float s = 0.f;
#pragma unroll
        for (int j = 0; j < 8; j++) s += leaky(acc[r][j] + bj[j]) * fj[j];
        atomicAdd(&rowsum[tx * 4 + r], s);
    }
    __syncthreads();
    if (tid < TM) {
        int row = row0 + tid;
        if (row < n) {
            int g = idx_at(batch, row);
            atomicAdd(&g_gsum[g * REP + (blockIdx.x & (REP - 1))], rowsum[tid]);
        }
    }
}

// ---------------- final: counts via binary search over sorted batch ----------------
__global__ void k_final(const void* __restrict__ batch, const float* __restrict__ fcb,
                        float* __restrict__ out, int n) {
    __shared__ int lb[G + 1];
    int t = threadIdx.x;
    if (t <= G) {
        int lo = 0, hi = n;
        while (lo < hi) {
            int mid = (lo + hi) >> 1;
            if (idx_at(batch, mid) < t) lo = mid + 1; else hi = mid;
        }
        lb[t] = lo;
    }
    __syncthreads();
    if (t < G) {
        float s = 0.f;
#pragma unroll
        for (int r = 0; r < REP; r++) s += g_gsum[t * REP + r];
        float c = (float)(lb[t + 1] - lb[t]);
        if (c < 1.f) c = 1.f;
        out[t] = s / c + fcb[0];
    }
}

// ---------------- launch ----------------
extern "C" void kernel_launch(void* const* d_in, const int* in_sizes, int n_in,
                              void* d_out, int out_size) {
    const float* x    = (const float*)d_in[0];
    const void*  ei   = d_in[1];
    const void*  bat  = d_in[2];
    const float* W1   = (const float*)d_in[3];
    const float* b1   = (const float*)d_in[4];
    const float* W2   = (const float*)d_in[5];
    const float* b2   = (const float*)d_in[6];
    const float* fcW  = (const float*)d_in[7];
    const float* fcb  = (const float*)d_in[8];
    float*       out  = (float*)d_out;

    int n = in_sizes[0] / D;
    int e = in_sizes[1] / 2;
    int nb = (n + SCB - 1) / SCB;

    float *h1, *h2;
    cudaGetSymbolAddress((void**)&h1, g_h1);
    cudaGetSymbolAddress((void**)&h2, g_h2);

    static cudaStream_t s2 = nullptr;
    static cudaEvent_t ev_fork = nullptr, ev_join = nullptr;
    if (!s2) {
        cudaStreamCreateWithFlags(&s2, cudaStreamNonBlocking);
        cudaEventCreateWithFlags(&ev_fork, cudaEventDisableTiming);
        cudaEventCreateWithFlags(&ev_join, cudaEventDisableTiming);
    }

    int tb = 256;

    // fork: layer-1 GEMM (x @ W1) runs parallel to CSR build
    cudaEventRecord(ev_fork, 0);
    cudaStreamWaitEvent(s2, ev_fork, 0);
    k_gemm<<<(n + BM - 1) / BM, 256, 0, s2>>>(x, W1, h1, n);
    cudaEventRecord(ev_join, s2);

    // CSR build on default stream
    k_init<<<(n + tb - 1) / tb, tb>>>((const int*)ei, n);
    k_deg<<<(e + tb - 1) / tb, tb>>>(ei, e);
    k_scan1<<<nb, SCB>>>(n);
    k_scan2<<<1, 128>>>(nb, n);
    k_scan3<<<nb, SCB>>>(n);
    k_fill<<<(e + tb - 1) / tb, tb>>>(ei, e);

    // join, then layer-1 aggregate (writes pre-scaled h2)
    cudaStreamWaitEvent(0, ev_join, 0);
    k_gather1<<<(n + 7) / 8, 256>>>((const float4*)h1, b1, (float4*)h2, n);

    // fused layer 2 + pool/fc
    k_fused2<<<(n + TM - 1) / TM, 256>>>((const float4*)h2, W2, b2, fcW, bat, n);

    k_final<<<1, 128>>>(bat, fcb, out, n);
}

// round 8
// speedup vs baseline: 1.3900x; 1.3900x over previous
#include <cuda_runtime.h>
#include <cstdint>

#define MAXN 100000
#define MAXE 1600000
#define D    128
#define G    64
#define REP  32
#define SCB  1024
#define TM   64      // nodes per fused-kernel block

// ---------------- device scratch ----------------
__device__ float g_h2[MAXN * D];        // pre-scaled layer-1 activation: dis_i*leaky(conv1_i)
__device__ int   g_deg[MAXN];
__device__ float g_dis[MAXN];
__device__ int   g_off[MAXN + 1];
__device__ int   g_cursor[MAXN];
__device__ int   g_adj[MAXE];           // src index
__device__ float g_wt[MAXE];            // edge norm (used by layer 1 only)
__device__ float g_gsum[G * REP];
__device__ int   g_bsum[128];
__device__ int   g_bbase[128];
__device__ int   g_is64;

// ---------------- dtype-agnostic index read ----------------
__device__ __forceinline__ int idx_at(const void* p, size_t i) {
    if (g_is64) return (int)((const long long*)p)[i];
    return ((const int*)p)[i];
}

// ---------------- init (+dtype detect) ----------------
__global__ void k_init(const int* __restrict__ ei32, int n) {
    int i = blockIdx.x * blockDim.x + threadIdx.x;
    if (i == 0) {
        int allz = 1;
        for (int j = 1; j < 32; j += 2)
            if (ei32[j] != 0) allz = 0;
        g_is64 = allz;
    }
    if (i < n) g_deg[i] = 1;
    if (i < G * REP) g_gsum[i] = 0.f;
}

// ---------------- in-degree count ----------------
__global__ void k_deg(const void* __restrict__ ei, int e) {
    int i = blockIdx.x * blockDim.x + threadIdx.x;
    if (i < e) atomicAdd(&g_deg[idx_at(ei, (size_t)e + i)], 1);
}

// ---------------- scan phase 1: block sums of (deg-1); also dis=rsqrt(deg) ----------------
__global__ void k_scan1(int n) {
    int i = blockIdx.x * SCB + threadIdx.x;
    int v = 0;
    if (i < n) {
        int d = g_deg[i];
        g_dis[i] = rsqrtf((float)d);
        v = d - 1;
    }
    int s = v;
#pragma unroll
    for (int o = 16; o; o >>= 1) s += __shfl_down_sync(0xffffffffu, s, o);
    __shared__ int ws[SCB / 32];
    int w = threadIdx.x >> 5, l = threadIdx.x & 31;
    if (l == 0) ws[w] = s;
    __syncthreads();
    if (w == 0) {
        int t = (l < SCB / 32) ? ws[l] : 0;
#pragma unroll
        for (int o = 16; o; o >>= 1) t += __shfl_down_sync(0xffffffffu, t, o);
        if (l == 0) g_bsum[blockIdx.x] = t;
    }
}

// ---------------- scan phase 2 ----------------
__global__ void k_scan2(int nb, int n) {
    __shared__ int sm[128];
    int t = threadIdx.x;
    int v = (t < nb) ? g_bsum[t] : 0;
    sm[t] = v;
    __syncthreads();
    for (int o = 1; o < 128; o <<= 1) {
        int u = (t >= o) ? sm[t - o] : 0;
        __syncthreads();
        if (t >= o) sm[t] += u;
        __syncthreads();
    }
    g_bbase[t] = sm[t] - v;
    if (t == 127) g_off[n] = sm[127];
}

// ---------------- scan phase 3 (seeds cursor = off) ----------------
__global__ void k_scan3(int n) {
    int i = blockIdx.x * SCB + threadIdx.x;
    int v = (i < n) ? (g_deg[i] - 1) : 0;
    int incl = v;
#pragma unroll
    for (int o = 1; o < 32; o <<= 1) {
        int u = __shfl_up_sync(0xffffffffu, incl, o);
        if ((threadIdx.x & 31) >= o) incl += u;
    }
    __shared__ int ws[SCB / 32];
    int w = threadIdx.x >> 5, l = threadIdx.x & 31;
    if (l == 31) ws[w] = incl;
    __syncthreads();
    if (w == 0) {
        int s = (l < SCB / 32) ? ws[l] : 0;
        int si = s;
#pragma unroll
        for (int o = 1; o < 32; o <<= 1) {
            int u = __shfl_up_sync(0xffffffffu, si, o);
            if (l >= o) si += u;
        }
        ws[l] = si - s;
    }
    __syncthreads();
    if (i < n) {
        int off = g_bbase[blockIdx.x] + ws[w] + (incl - v);
        g_off[i] = off;
        g_cursor[i] = off;
    }
}

// ---------------- fill CSR (split arrays) ----------------
__global__ void k_fill(const void* __restrict__ ei, int e) {
    int i = blockIdx.x * blockDim.x + threadIdx.x;
    if (i < e) {
        int r = idx_at(ei, i);
        int c = idx_at(ei, (size_t)e + i);
        int pos = atomicAdd(&g_cursor[c], 1);
        g_adj[pos] = r;
        g_wt[pos] = g_dis[r] * g_dis[c];
    }
}

// ---------------- fused layer: gather -> smem -> FFMA GEMM -> epilogue ----------------
// agg(in@W) == agg(in)@W (aggregation linear): gather first, GEMM second.
__device__ __forceinline__ float leaky(float x) { return x >= 0.f ? x : 0.01f * x; }

template <int POOL, int WEIGHTED>
__global__ __launch_bounds__(256, 3) void k_fused(
    const float4* __restrict__ in, const float* __restrict__ W,
    const float* __restrict__ bias, const float* __restrict__ fcW,
    const void* __restrict__ batch, float4* __restrict__ hout, int n)
{
    __shared__ float At[D][66];     // feature-major agg tile: At[feature][node]
    __shared__ float Ws[16][D];
    __shared__ float rowsum[TM];

    int tid = threadIdx.x;
    int warp = tid >> 5, lane = tid & 31;
    int row0 = blockIdx.x * TM;

    // ---- phase 1: gather (warp per node, lane = feature quad), 4-wide MLP ----
    for (int nd = warp; nd < TM; nd += 8) {
        int node = row0 + nd;
        float4 acc = make_float4(0.f, 0.f, 0.f, 0.f);
        if (node < n) {
            float di = g_dis[node];
            float4 v = in[(size_t)node * 32 + lane];
            if (WEIGHTED) {
                float self = di * di;
                acc.x = v.x * self; acc.y = v.y * self;
                acc.z = v.z * self; acc.w = v.w * self;
            } else {
                acc = v;            // pre-scaled input: plain sum
            }
            int s = g_off[node], e = g_off[node + 1];
            int j = s;
            for (; j + 4 <= e; j += 4) {
                int s0 = g_adj[j], s1 = g_adj[j + 1], s2 = g_adj[j + 2], s3 = g_adj[j + 3];
                float4 v0 = in[(size_t)s0 * 32 + lane];
                float4 v1 = in[(size_t)s1 * 32 + lane];
                float4 v2 = in[(size_t)s2 * 32 + lane];
                float4 v3 = in[(size_t)s3 * 32 + lane];
                if (WEIGHTED) {
                    float w0 = g_wt[j], w1 = g_wt[j + 1], w2 = g_wt[j + 2], w3 = g_wt[j + 3];
                    acc.x += v0.x * w0 + v1.x * w1 + v2.x * w2 + v3.x * w3;
                    acc.y += v0.y * w0 + v1.y * w1 + v2.y * w2 + v3.y * w3;
                    acc.z += v0.z * w0 + v1.z * w1 + v2.z * w2 + v3.z * w3;
                    acc.w += v0.w * w0 + v1.w * w1 + v2.w * w2 + v3.w * w3;
                } else {
                    acc.x += v0.x + v1.x + v2.x + v3.x;
                    acc.y += v0.y + v1.y + v2.y + v3.y;
                    acc.z += v0.z + v1.z + v2.z + v3.z;
                    acc.w += v0.w + v1.w + v2.w + v3.w;
                }
            }
            for (; j < e; j++) {
                int s0 = g_adj[j];
                float4 v0 = in[(size_t)s0 * 32 + lane];
                if (WEIGHTED) {
                    float w0 = g_wt[j];
                    acc.x += v0.x * w0; acc.y += v0.y * w0;
                    acc.z += v0.z * w0; acc.w += v0.w * w0;
                } else {
                    acc.x += v0.x; acc.y += v0.y; acc.z += v0.z; acc.w += v0.w;
                }
            }
            if (!WEIGHTED) {        // finish dis_i * (sum)
                acc.x *= di; acc.y *= di; acc.z *= di; acc.w *= di;
            }
        }
        int c = lane * 4;
        At[c + 0][nd] = acc.x;
        At[c + 1][nd] = acc.y;
        At[c + 2][nd] = acc.z;
        At[c + 3][nd] = acc.w;
    }
    if (POOL && tid < TM) rowsum[tid] = 0.f;

    // ---- phase 2: GEMM C[64x128] = At^T @ W ----
    int tx = tid & 15;              // rows tx*4 .. tx*4+3
    int ty = tid >> 4;              // cols ty*8 .. ty*8+7
    float acc[4][8];
#pragma unroll
    for (int r = 0; r < 4; r++)
#pragma unroll
        for (int j = 0; j < 8; j++) acc[r][j] = 0.f;

    for (int kb = 0; kb < D; kb += 16) {
#pragma unroll
        for (int l = 0; l < 2; l++) {
            int idx4 = tid + l * 256;
            int k = idx4 >> 5, c4 = idx4 & 31;
            *(float4*)&Ws[k][c4 * 4] = *(const float4*)&W[(size_t)(kb + k) * D + c4 * 4];
        }
        __syncthreads();
#pragma unroll
        for (int k = 0; k < 16; k++) {
            float a[4], b[8];
#pragma unroll
            for (int r = 0; r < 4; r++) a[r] = At[kb + k][tx * 4 + r];
            *(float4*)&b[0] = *(float4*)&Ws[k][ty * 8];
            *(float4*)&b[4] = *(float4*)&Ws[k][ty * 8 + 4];
#pragma unroll
            for (int r = 0; r < 4; r++)
#pragma unroll
                for (int j = 0; j < 8; j++) acc[r][j] += a[r] * b[j];
        }
        __syncthreads();
    }

    // ---- phase 3: epilogue ----
    if (!POOL) {
        // store h2 PRE-SCALED: h2 = dis_row * leaky(C + b1)
#pragma unroll
        for (int r = 0; r < 4; r++) {
            int row = row0 + tx * 4 + r;
            if (row < n) {
                float dr = g_dis[row];
                float4 o0, o1;
                o0.x = dr * leaky(acc[r][0] + bias[ty * 8 + 0]);
                o0.y = dr * leaky(acc[r][1] + bias[ty * 8 + 1]);
                o0.z = dr * leaky(acc[r][2] + bias[ty * 8 + 2]);
                o0.w = dr * leaky(acc[r][3] + bias[ty * 8 + 3]);
                o1.x = dr * leaky(acc[r][4] + bias[ty * 8 + 4]);
                o1.y = dr * leaky(acc[r][5] + bias[ty * 8 + 5]);
                o1.z = dr * leaky(acc[r][6] + bias[ty * 8 + 6]);
                o1.w = dr * leaky(acc[r][7] + bias[ty * 8 + 7]);
                hout[(size_t)row * 32 + ty * 2] = o0;
                hout[(size_t)row * 32 + ty * 2 + 1] = o1;
            }
        }
    } else {
        __syncthreads();
        float fj[8], bj[8];
#pragma unroll
        for (int j = 0; j < 8; j++) { fj[j] = fcW[ty * 8 + j]; bj[j] = bias[ty * 8 + j]; }
#pragma unroll
        for (int r = 0; r < 4; r++) {
            float s = 0.f;
#pragma unroll
            for (int j = 0; j < 8; j++) s += leaky(acc[r][j] + bj[j]) * fj[j];
            atomicAdd(&rowsum[tx * 4 + r], s);
        }
        __syncthreads();
        if (tid < TM) {
            int row = row0 + tid;
            if (row < n) {
                int g = idx_at(batch, row);
                atomicAdd(&g_gsum[g * REP + (blockIdx.x & (REP - 1))], rowsum[tid]);
            }
        }
    }
}

// ---------------- final ----------------
__global__ void k_final(const void* __restrict__ batch, const float* __restrict__ fcb,
                        float* __restrict__ out, int n) {
    __shared__ int lb[G + 1];
    int t = threadIdx.x;
    if (t <= G) {
        int lo = 0, hi = n;
        while (lo < hi) {
            int mid = (lo + hi) >> 1;
            if (idx_at(batch, mid) < t) lo = mid + 1; else hi = mid;
        }
        lb[t] = lo;
    }
    __syncthreads();
    if (t < G) {
        float s = 0.f;
#pragma unroll
        for (int r = 0; r < REP; r++) s += g_gsum[t * REP + r];
        float c = (float)(lb[t + 1] - lb[t]);
        if (c < 1.f) c = 1.f;
        out[t] = s / c + fcb[0];
    }
}

// ---------------- launch ----------------
extern "C" void kernel_launch(void* const* d_in, const int* in_sizes, int n_in,
                              void* d_out, int out_size) {
    const float* x    = (const float*)d_in[0];
    const void*  ei   = d_in[1];
    const void*  bat  = d_in[2];
    const float* W1   = (const float*)d_in[3];
    const float* b1   = (const float*)d_in[4];
    const float* W2   = (const float*)d_in[5];
    const float* b2   = (const float*)d_in[6];
    const float* fcW  = (const float*)d_in[7];
    const float* fcb  = (const float*)d_in[8];
    float*       out  = (float*)d_out;

    int n = in_sizes[0] / D;
    int e = in_sizes[1] / 2;
    int nb = (n + SCB - 1) / SCB;

    float* h2;
    cudaGetSymbolAddress((void**)&h2, g_h2);

    int tb = 256;
    // CSR build
    k_init<<<(n + tb - 1) / tb, tb>>>((const int*)ei, n);
    k_deg<<<(e + tb - 1) / tb, tb>>>(ei, e);
    k_scan1<<<nb, SCB>>>(n);
    k_scan2<<<1, 128>>>(nb, n);
    k_scan3<<<nb, SCB>>>(n);
    k_fill<<<(e + tb - 1) / tb, tb>>>(ei, e);

    int gblk = (n + TM - 1) / TM;
    // layer 1: h2 = dis .* leaky(agg(x)@W1 + b1)   (weighted gather)
    k_fused<0, 1><<<gblk, 256>>>((const float4*)x, W1, b1, nullptr, nullptr,
                                 (float4*)h2, n);
    // layer 2 + pool/fc (pure-sum gather over pre-scaled h2)
    k_fused<1, 0><<<gblk, 256>>>((const float4*)h2, W2, b2, fcW, bat, nullptr, n);

    k_final<<<1, 128>>>(bat, fcb, out, n);
}